// round 10
// baseline (speedup 1.0000x reference)
#include <cuda_runtime.h>
#include <cuda_bf16.h>
#include <math.h>
#include <stdint.h>

#define N_USERS 10000
#define N_ITEMS 30000
#define N_NODES 40000
#define HID     256
#define N_EDGES 500000
#define AH      32

// ---------------- scratch (static device allocations only) ----------------
__device__ float g_U1[N_USERS * AH];
__device__ float g_I1[N_ITEMS * AH];
__device__ int   g_ksrc[N_EDGES];
__device__ int   g_kdst[N_EDGES];
__device__ float g_deg[N_USERS];
__device__ float g_dinv[N_USERS];
__device__ float g_xw[(size_t)N_USERS * HID];        // only user rows needed by scatter
__device__ int   g_cnt[1];                           // kept-edge count
__device__ int   g_done;                             // finished-block counter for k_edge
__device__ unsigned long long g_maxpack;             // (w_bits<<32) | ~e
// bf16-split operands (K-major)
__device__ __align__(16) __nv_bfloat16 g_Xhi[(size_t)N_NODES * HID];
__device__ __align__(16) __nv_bfloat16 g_Xlo[(size_t)N_NODES * HID];
__device__ __align__(16) __nv_bfloat16 g_Whi[HID * HID];       // gcn W^T: [n][k]
__device__ __align__(16) __nv_bfloat16 g_Wlo[HID * HID];
__device__ __align__(16) __nv_bfloat16 g_A1hi[2 * AH * HID];   // attn W1^T: [half][n][k]
__device__ __align__(16) __nv_bfloat16 g_A1lo[2 * AH * HID];

// ---------------- helpers ---------------------------------------------------
__device__ __forceinline__ uint32_t smem_u32(const void* p) {
    uint32_t a;
    asm("{ .reg .u64 t; cvta.to.shared.u64 t, %1; cvt.u32.u64 %0, t; }" : "=r"(a) : "l"(p));
    return a;
}
__device__ __forceinline__ void ldsm4(uint32_t* f, uint32_t addr) {
    asm volatile("ldmatrix.sync.aligned.m8n8.x4.shared.b16 {%0,%1,%2,%3}, [%4];"
        : "=r"(f[0]), "=r"(f[1]), "=r"(f[2]), "=r"(f[3]) : "r"(addr));
}
__device__ __forceinline__ void mma16816(float* d, const uint32_t* a, uint32_t b0, uint32_t b1) {
    asm volatile("mma.sync.aligned.m16n8k16.row.col.f32.bf16.bf16.f32 "
        "{%0,%1,%2,%3}, {%4,%5,%6,%7}, {%8,%9}, {%0,%1,%2,%3};"
        : "+f"(d[0]), "+f"(d[1]), "+f"(d[2]), "+f"(d[3])
        : "r"(a[0]), "r"(a[1]), "r"(a[2]), "r"(a[3]), "r"(b0), "r"(b1));
}
#define CP_ASYNC16(s, g) asm volatile("cp.async.cg.shared.global [%0], [%1], 16;" :: "r"(s), "l"(g))
#define CP_COMMIT()      asm volatile("cp.async.commit_group;" ::: "memory")
#define CP_WAIT(n)       asm volatile("cp.async.wait_group %0;" :: "n"(n) : "memory")

__device__ __forceinline__ uint32_t swaddr(uint32_t base, int r, int kb) {
    return base + (uint32_t)(r * 128) + (uint32_t)(((kb ^ (r & 7)) << 4));
}
__device__ __forceinline__ uint32_t bits2(__nv_bfloat162 h) {
    return *reinterpret_cast<uint32_t*>(&h);
}

// ---------------- K_prep: reset + weight splits (small) -------------------
__global__ __launch_bounds__(256) void k_prep(
    const float* __restrict__ W, const float* __restrict__ W1) {
    const int i = blockIdx.x * blockDim.x + threadIdx.x;
    if (i < HID * HID) {                        // gcn W^T split
        int n = i >> 8, k = i & 255;
        float v = W[k * HID + n];
        __nv_bfloat16 h = __float2bfloat16(v);
        g_Whi[i] = h;
        g_Wlo[i] = __float2bfloat16(v - __bfloat162float(h));
    }
    if (i < 2 * AH * HID) {                     // attn W1^T split: [half][n][k]
        int half = i >> 13, rem = i & 8191;
        int n = rem >> 8, k = rem & 255;
        float v = W1[(half * HID + k) * AH + n];
        __nv_bfloat16 h = __float2bfloat16(v);
        g_A1hi[i] = h;
        g_A1lo[i] = __float2bfloat16(v - __bfloat162float(h));
    }
    if (i < N_USERS) g_deg[i] = 1.0f;
    if (i == 0) { g_cnt[0] = 0; g_done = 0; g_maxpack = 0ull; }
}

// ---------------- K1: attention layer-1 + X bf16-split producer -----------
// CTA: 256 rows x 32 cols, K=256 in 4 chunks of 64.
// smem: B hi/lo (32KB) | fp32 X stage x2 (128KB) | bf16 A hi/lo (64KB) = 224KB
#define AC_BH    0
#define AC_BL    16384
#define AC_F0    32768
#define AC_FST   65536
#define AC_AHI   163840
#define AC_ALO   196608
#define AC_SMEM  229376
#define N_UBLK   ((N_USERS + 255) / 256)        // 40
#define N_IBLK   ((N_ITEMS + 255) / 256)        // 118

__device__ __forceinline__ void ac_stage_f(uint32_t sF, const float* __restrict__ base,
                                           int r0rel, int ko, int rmaxrel, int t) {
    #pragma unroll
    for (int i = t; i < 4096; i += 256) {       // 16 cp.async per thread
        int r = i >> 4, j = i & 15;
        int gr = r0rel + r; if (gr > rmaxrel) gr = rmaxrel;
        CP_ASYNC16(sF + (uint32_t)(r * 256 + j * 16),
                   base + (size_t)gr * HID + ko + j * 4);
    }
}

__global__ __launch_bounds__(256, 1) void k_attn_conv(
    const float* __restrict__ ue, const float* __restrict__ ie,
    const float* __restrict__ b1) {
    extern __shared__ char smem[];
    const int t = threadIdx.x, l = t & 31, wrp = t >> 5;
    const int b = blockIdx.x;
    const int half = (b < N_UBLK) ? 0 : 1;
    const int row0 = half ? (N_USERS + (b - N_UBLK) * 256) : b * 256;
    const int rmax = half ? (N_NODES - 1) : (N_USERS - 1);
    const float* xbase = half ? ie : ue;
    const int rbase = half ? N_USERS : 0;

    const uint32_t sb = smem_u32(smem);

    {   // B: 32 n-rows x 256 k, chunk-major (chunk c -> 32 rows x 128B)
        const __nv_bfloat16* srcH = g_A1hi + half * (AH * HID);
        const __nv_bfloat16* srcL = g_A1lo + half * (AH * HID);
        #pragma unroll
        for (int i = t; i < 1024; i += 256) {
            int c = i >> 8, n = (i >> 3) & 31, j = i & 7;
            size_t go = (size_t)n * HID + c * 64 + j * 8;
            uint32_t so = swaddr(c * 4096, n, j);
            CP_ASYNC16(sb + AC_BH + so, srcH + go);
            CP_ASYNC16(sb + AC_BL + so, srcL + go);
        }
    }
    ac_stage_f(sb + AC_F0, xbase, row0 - rbase, 0, rmax - rbase, t);
    CP_COMMIT();

    float acc[2][4][4] = {};
    const int rA = wrp * 32 + (l & 15);         // warp tile: 32 rows x 32 cols
    const int khalf = l >> 4;

    for (int c = 0; c < 4; c++) {
        if (c < 3) {
            ac_stage_f(sb + AC_F0 + ((c + 1) & 1) * AC_FST, xbase,
                       row0 - rbase, (c + 1) * 64, rmax - rbase, t);
            CP_COMMIT();
            CP_WAIT(1);
        } else {
            CP_WAIT(0);
        }
        __syncthreads();                        // F_c ready; sA free (prev MMA done)

        // convert fp32 chunk -> bf16 hi/lo: swizzled sA tiles + global splits
        const char* fB = smem + AC_F0 + (c & 1) * AC_FST;
        const int ko = c * 64;
        #pragma unroll
        for (int i = t; i < 2048; i += 256) {   // 8 tasks x 8 floats
            int r = i >> 3, j = i & 7;
            int gr = row0 + r; if (gr > rmax) gr = rmax;
            float4 v0 = *(const float4*)(fB + r * 256 + j * 32);
            float4 v1 = *(const float4*)(fB + r * 256 + j * 32 + 16);
            __nv_bfloat162 h0 = __float22bfloat162_rn(make_float2(v0.x, v0.y));
            __nv_bfloat162 h1 = __float22bfloat162_rn(make_float2(v0.z, v0.w));
            __nv_bfloat162 h2 = __float22bfloat162_rn(make_float2(v1.x, v1.y));
            __nv_bfloat162 h3 = __float22bfloat162_rn(make_float2(v1.z, v1.w));
            float2 f0 = __bfloat1622float2(h0), f1 = __bfloat1622float2(h1);
            float2 f2 = __bfloat1622float2(h2), f3 = __bfloat1622float2(h3);
            __nv_bfloat162 l0 = __float22bfloat162_rn(make_float2(v0.x - f0.x, v0.y - f0.y));
            __nv_bfloat162 l1 = __float22bfloat162_rn(make_float2(v0.z - f1.x, v0.w - f1.y));
            __nv_bfloat162 l2 = __float22bfloat162_rn(make_float2(v1.x - f2.x, v1.y - f2.y));
            __nv_bfloat162 l3 = __float22bfloat162_rn(make_float2(v1.z - f3.x, v1.w - f3.y));
            uint4 H = make_uint4(bits2(h0), bits2(h1), bits2(h2), bits2(h3));
            uint4 L = make_uint4(bits2(l0), bits2(l1), bits2(l2), bits2(l3));
            uint32_t so = swaddr(0, r, j);
            *(uint4*)(smem + AC_AHI + so) = H;
            *(uint4*)(smem + AC_ALO + so) = L;
            const size_t go = (size_t)gr * HID + ko + j * 8;
            *(uint4*)(g_Xhi + go) = H;
            *(uint4*)(g_Xlo + go) = L;
        }
        __syncthreads();                        // sA populated

        #pragma unroll
        for (int ks = 0; ks < 4; ks++) {
            const int kb = ks * 2 + khalf;
            uint32_t Ah[2][4], Al[2][4], Bh[2][4], Bl[2][4];
            ldsm4(Ah[0], swaddr(sb + AC_AHI, rA,      kb));
            ldsm4(Ah[1], swaddr(sb + AC_AHI, rA + 16, kb));
            ldsm4(Al[0], swaddr(sb + AC_ALO, rA,      kb));
            ldsm4(Al[1], swaddr(sb + AC_ALO, rA + 16, kb));
            ldsm4(Bh[0], swaddr(sb + AC_BH + c * 4096, (l & 15),      kb));
            ldsm4(Bh[1], swaddr(sb + AC_BH + c * 4096, 16 + (l & 15), kb));
            ldsm4(Bl[0], swaddr(sb + AC_BL + c * 4096, (l & 15),      kb));
            ldsm4(Bl[1], swaddr(sb + AC_BL + c * 4096, 16 + (l & 15), kb));
            #pragma unroll
            for (int mi = 0; mi < 2; mi++)
                #pragma unroll
                for (int nj = 0; nj < 4; nj++) {
                    const int nb = nj >> 1, p = nj & 1;
                    mma16816(acc[mi][nj], Ah[mi], Bh[nb][p], Bh[nb][p + 2]);
                    mma16816(acc[mi][nj], Ah[mi], Bl[nb][p], Bl[nb][p + 2]);
                    mma16816(acc[mi][nj], Al[mi], Bh[nb][p], Bh[nb][p + 2]);
                }
        }
    }

    #pragma unroll
    for (int mi = 0; mi < 2; mi++) {
        #pragma unroll
        for (int h = 0; h < 2; h++) {
            const int r = row0 + wrp * 32 + mi * 16 + (l >> 2) + h * 8;
            if (r > rmax) continue;
            #pragma unroll
            for (int nj = 0; nj < 4; nj++) {
                const int col = nj * 8 + 2 * (l & 3);
                float x = acc[mi][nj][h * 2 + 0];
                float y = acc[mi][nj][h * 2 + 1];
                if (half) {
                    x += b1[col]; y += b1[col + 1];
                    *(float2*)(g_I1 + (size_t)(r - N_USERS) * AH + col) = make_float2(x, y);
                } else {
                    *(float2*)(g_U1 + (size_t)r * AH + col) = make_float2(x, y);
                }
            }
        }
    }
}

// ---------------- K2: edge MLP + denoise + compact + fallback + dinv ------
__global__ __launch_bounds__(256) void k_edge(
    const int* __restrict__ ei, const float* __restrict__ W2,
    const float* __restrict__ b2, float* __restrict__ out_w) {
    __shared__ float w2s[32];
    __shared__ float b2s;
    __shared__ int s_last;
    if (threadIdx.x < 32) w2s[threadIdx.x] = W2[threadIdx.x];
    if (threadIdx.x == 0) b2s = b2[0];
    __syncthreads();

    const int e = blockIdx.x * blockDim.x + threadIdx.x;
    bool pass = false;
    int s = 0, d = 0;
    unsigned long long pack = 0ull;
    if (e < N_EDGES) {
        s = ei[e];
        d = ei[N_EDGES + e];
        const float4* up = (const float4*)(g_U1 + (size_t)s * AH);
        const float4* ip = (const float4*)(g_I1 + (size_t)d * AH);
        float logit = b2s;
        #pragma unroll
        for (int q = 0; q < 8; q++) {
            float4 u = up[q], v = ip[q];
            float h;
            h = u.x + v.x; h = h > 0.0f ? h : 0.2f * h; logit = fmaf(h, w2s[q * 4 + 0], logit);
            h = u.y + v.y; h = h > 0.0f ? h : 0.2f * h; logit = fmaf(h, w2s[q * 4 + 1], logit);
            h = u.z + v.z; h = h > 0.0f ? h : 0.2f * h; logit = fmaf(h, w2s[q * 4 + 2], logit);
            h = u.w + v.w; h = h > 0.0f ? h : 0.2f * h; logit = fmaf(h, w2s[q * 4 + 3], logit);
        }
        float w = 1.0f / (1.0f + expf(-logit));
        pass = (w > 0.8f);
        out_w[e] = pass ? w : 0.0f;
        pack = ((unsigned long long)__float_as_uint(w) << 32)
             | (unsigned long long)(~(unsigned)e);
    }
    // argmax reduce (for fallback)
    unsigned long long pk = pack;
    #pragma unroll
    for (int off = 16; off; off >>= 1) {
        unsigned long long o = __shfl_down_sync(0xffffffffu, pk, off);
        if (o > pk) pk = o;
    }
    const int lane = threadIdx.x & 31;
    if (lane == 0) atomicMax(&g_maxpack, pk);
    // warp-aggregated compaction (no early return: all threads reach barriers)
    unsigned m = __ballot_sync(0xffffffffu, pass);
    if (m) {
        const int leader = __ffs(m) - 1;
        int base = 0;
        if (lane == leader) base = atomicAdd(&g_cnt[0], __popc(m));
        base = __shfl_sync(0xffffffffu, base, leader);
        if (pass) {
            const int rank = __popc(m & ((1u << lane) - 1));
            g_ksrc[base + rank] = s;
            g_kdst[base + rank] = d;
            atomicAdd(&g_deg[d], 1.0f);
        }
    }
    // last-block: fallback + dinv (threadfence + done-counter protocol)
    __threadfence();
    __syncthreads();
    if (threadIdx.x == 0)
        s_last = (atomicAdd(&g_done, 1) == (int)gridDim.x - 1) ? 1 : 0;
    __syncthreads();
    if (s_last) {
        if (threadIdx.x == 0 && g_cnt[0] == 0) {
            const unsigned long long p = g_maxpack;
            const int fe = (int)(~(unsigned)(p & 0xffffffffull));
            out_w[fe] = __uint_as_float((unsigned)(p >> 32));
            const int fs = ei[fe];
            const int fd = ei[N_EDGES + fe];
            g_ksrc[0] = fs;
            g_kdst[0] = fd;
            g_cnt[0] = 1;
            g_deg[fd] += 1.0f;
        }
        __syncthreads();
        #pragma unroll 4
        for (int i = threadIdx.x; i < N_USERS; i += 256)
            g_dinv[i] = rsqrtf(g_deg[i]);
    }
}

// ---------------- K5: HMMA bf16x3 GEMM, fused self-loop + bias ------------
#define GT      16384
#define GSTAGE  (4 * GT)
#define GSMEM   (2 * GSTAGE)

__device__ __forceinline__ void stage_all(char* dst, int m0, int n0, int ko, int t) {
    uint32_t sb = smem_u32(dst);
    #pragma unroll
    for (int i = t; i < 1024; i += 256) {
        int r = i >> 3, kb = i & 7;
        int gr = m0 + r; if (gr > N_NODES - 1) gr = N_NODES - 1;
        size_t go = (size_t)gr * HID + ko + kb * 8;
        uint32_t so = sb + (uint32_t)(r * 128) + (uint32_t)(((kb ^ (r & 7)) << 4));
        CP_ASYNC16(so,          g_Xhi + go);
        CP_ASYNC16(so + GT,     g_Xlo + go);
        int br = n0 + r;
        size_t bo = (size_t)br * HID + ko + kb * 8;
        CP_ASYNC16(so + 2 * GT, g_Whi + bo);
        CP_ASYNC16(so + 3 * GT, g_Wlo + bo);
    }
}

__global__ __launch_bounds__(256, 1) void k_gemm(const float* __restrict__ gb,
                                                 float* __restrict__ out) {
    extern __shared__ char smem[];
    const int t = threadIdx.x;
    const int l = t & 31, wrp = t >> 5;
    const int wm = wrp & 3, wn = wrp >> 2;
    const int m0 = blockIdx.x * 128, n0 = blockIdx.y * 128;
    const uint32_t sbase = smem_u32(smem);

    stage_all(smem, m0, n0, 0, t);
    CP_COMMIT();

    float acc[2][8][4] = {};
    const int rA = wm * 32 + (l & 15);
    const int rB = wn * 64 + (l & 15);
    const int khalf = l >> 4;

    for (int c = 0; c < 4; c++) {
        if (c < 3) {
            stage_all(smem + ((c + 1) & 1) * GSTAGE, m0, n0, (c + 1) * 64, t);
            CP_COMMIT();
            CP_WAIT(1);
        } else {
            CP_WAIT(0);
        }
        __syncthreads();
        const uint32_t sb  = sbase + (c & 1) * GSTAGE;
        const uint32_t sAh = sb, sAl = sb + GT, sBh = sb + 2 * GT, sBl = sb + 3 * GT;
        #pragma unroll
        for (int ks = 0; ks < 4; ks++) {
            const int kb = ks * 2 + khalf;
            uint32_t A[2][4], Bh[4][4], Bl[4][4];
            ldsm4(A[0], swaddr(sAh, rA,      kb));
            ldsm4(A[1], swaddr(sAh, rA + 16, kb));
            #pragma unroll
            for (int nj = 0; nj < 4; nj++) {
                ldsm4(Bh[nj], swaddr(sBh, rB + nj * 16, kb));
                ldsm4(Bl[nj], swaddr(sBl, rB + nj * 16, kb));
            }
            #pragma unroll
            for (int mi = 0; mi < 2; mi++)
                #pragma unroll
                for (int nj = 0; nj < 4; nj++) {
                    mma16816(acc[mi][nj * 2],     A[mi], Bh[nj][0], Bh[nj][2]);
                    mma16816(acc[mi][nj * 2 + 1], A[mi], Bh[nj][1], Bh[nj][3]);
                    mma16816(acc[mi][nj * 2],     A[mi], Bl[nj][0], Bl[nj][2]);
                    mma16816(acc[mi][nj * 2 + 1], A[mi], Bl[nj][1], Bl[nj][3]);
                }
            ldsm4(A[0], swaddr(sAl, rA,      kb));
            ldsm4(A[1], swaddr(sAl, rA + 16, kb));
            #pragma unroll
            for (int mi = 0; mi < 2; mi++)
                #pragma unroll
                for (int nj = 0; nj < 4; nj++) {
                    mma16816(acc[mi][nj * 2],     A[mi], Bh[nj][0], Bh[nj][2]);
                    mma16816(acc[mi][nj * 2 + 1], A[mi], Bh[nj][1], Bh[nj][3]);
                }
        }
        __syncthreads();
    }

    #pragma unroll
    for (int mi = 0; mi < 2; mi++) {
        #pragma unroll
        for (int h = 0; h < 2; h++) {
            const int row = m0 + wm * 32 + mi * 16 + (l >> 2) + h * 8;
            if (row >= N_NODES) continue;
            const bool isU = (row < N_USERS);
            const float dv  = isU ? g_dinv[row] : 1.0f;
            const float dsq = dv * dv;
            #pragma unroll
            for (int ni = 0; ni < 8; ni++) {
                const int col = n0 + wn * 64 + ni * 8 + 2 * (l & 3);
                const float x = acc[mi][ni][h * 2 + 0];
                const float y = acc[mi][ni][h * 2 + 1];
                const size_t off = (size_t)row * HID + col;
                if (isU) *(float2*)(g_xw + off) = make_float2(x, y);   // scatter reads users only
                const float2 bb = *(const float2*)(gb + col);
                *(float2*)(out + off) = make_float2(fmaf(x, dsq, bb.x), fmaf(y, dsq, bb.y));
            }
        }
    }
}

// ---------------- K6: scatter messages (vectorized L2 reductions) ---------
__global__ __launch_bounds__(256) void k_scatter(float* __restrict__ out) {
    const int kept = g_cnt[0];
    const long long total = (long long)kept * (HID / 4);
    const long long stride = (long long)gridDim.x * blockDim.x;
    for (long long idx = (long long)blockIdx.x * blockDim.x + threadIdx.x;
         idx < total; idx += stride) {
        const int i = (int)(idx >> 6);
        const int q = (int)(idx & 63);
        const int s = g_ksrc[i];
        const int d = g_kdst[i];
        const float coef = g_dinv[s] * g_dinv[d];
        float4 v = *(const float4*)(g_xw + (size_t)s * HID + q * 4);
        float* p = out + (size_t)d * HID + q * 4;
        asm volatile("red.global.add.v4.f32 [%0], {%1,%2,%3,%4};"
                     :: "l"(p), "f"(v.x * coef), "f"(v.y * coef),
                        "f"(v.z * coef), "f"(v.w * coef)
                     : "memory");
    }
}

// ---------------- host launch ---------------------------------------------
extern "C" void kernel_launch(void* const* d_in, const int* in_sizes, int n_in,
                              void* d_out, int out_size) {
    const float* ue = (const float*)d_in[0];
    const float* ie = (const float*)d_in[1];
    const int*   ei = (const int*)  d_in[2];
    const float* W1 = (const float*)d_in[3];
    const float* b1 = (const float*)d_in[4];
    const float* W2 = (const float*)d_in[5];
    const float* b2 = (const float*)d_in[6];
    const float* gW = (const float*)d_in[7];
    const float* gb = (const float*)d_in[8];
    float* out   = (float*)d_out;
    float* out_w = out + (size_t)N_NODES * HID;

    cudaFuncSetAttribute(k_gemm,      cudaFuncAttributeMaxDynamicSharedMemorySize, GSMEM);
    cudaFuncSetAttribute(k_attn_conv, cudaFuncAttributeMaxDynamicSharedMemorySize, AC_SMEM);

    k_prep<<<(HID * HID + 255) / 256, 256>>>(gW, W1);
    k_attn_conv<<<N_UBLK + N_IBLK, 256, AC_SMEM>>>(ue, ie, b1);
    k_edge<<<(N_EDGES + 255) / 256, 256>>>(ei, W2, b2, out_w);
    dim3 gg((N_NODES + 127) / 128, 2);
    k_gemm<<<gg, 256, GSMEM>>>(gb, out);
    k_scatter<<<1024, 256>>>(out);
}

// round 13
// speedup vs baseline: 1.0140x; 1.0140x over previous
#include <cuda_runtime.h>
#include <cuda_bf16.h>
#include <math.h>
#include <stdint.h>

#define N_USERS 10000
#define N_ITEMS 30000
#define N_NODES 40000
#define HID     256
#define N_EDGES 500000
#define AH      32

// ---------------- scratch (static device allocations only) ----------------
__device__ float g_U1[N_USERS * AH];
__device__ float g_I1[N_ITEMS * AH];
__device__ int   g_ksrc[N_EDGES];
__device__ int   g_kdst[N_EDGES];
__device__ float g_deg[N_USERS];
__device__ float g_dinv[N_USERS];
__device__ float g_xw[(size_t)N_USERS * HID];        // only user rows needed by scatter
__device__ int   g_cnt[1];                           // kept-edge count
__device__ int   g_done;                             // finished-block counter for k_edge
__device__ unsigned long long g_maxpack;             // (w_bits<<32) | ~e
// bf16-split operands (K-major)
__device__ __align__(16) __nv_bfloat16 g_Xhi[(size_t)N_NODES * HID];
__device__ __align__(16) __nv_bfloat16 g_Xlo[(size_t)N_NODES * HID];
__device__ __align__(16) __nv_bfloat16 g_Whi[HID * HID];       // gcn W^T: [n][k]
__device__ __align__(16) __nv_bfloat16 g_Wlo[HID * HID];
__device__ __align__(16) __nv_bfloat16 g_A1hi[2 * AH * HID];   // attn W1^T: [half][n][k]
__device__ __align__(16) __nv_bfloat16 g_A1lo[2 * AH * HID];

// ---------------- helpers ---------------------------------------------------
__device__ __forceinline__ uint32_t smem_u32(const void* p) {
    uint32_t a;
    asm("{ .reg .u64 t; cvta.to.shared.u64 t, %1; cvt.u32.u64 %0, t; }" : "=r"(a) : "l"(p));
    return a;
}
__device__ __forceinline__ void ldsm4(uint32_t* f, uint32_t addr) {
    asm volatile("ldmatrix.sync.aligned.m8n8.x4.shared.b16 {%0,%1,%2,%3}, [%4];"
        : "=r"(f[0]), "=r"(f[1]), "=r"(f[2]), "=r"(f[3]) : "r"(addr));
}
__device__ __forceinline__ void mma16816(float* d, const uint32_t* a, uint32_t b0, uint32_t b1) {
    asm volatile("mma.sync.aligned.m16n8k16.row.col.f32.bf16.bf16.f32 "
        "{%0,%1,%2,%3}, {%4,%5,%6,%7}, {%8,%9}, {%0,%1,%2,%3};"
        : "+f"(d[0]), "+f"(d[1]), "+f"(d[2]), "+f"(d[3])
        : "r"(a[0]), "r"(a[1]), "r"(a[2]), "r"(a[3]), "r"(b0), "r"(b1));
}
#define CP_ASYNC16(s, g) asm volatile("cp.async.cg.shared.global [%0], [%1], 16;" :: "r"(s), "l"(g))
#define CP_COMMIT()      asm volatile("cp.async.commit_group;" ::: "memory")
#define CP_WAIT(n)       asm volatile("cp.async.wait_group %0;" :: "n"(n) : "memory")

__device__ __forceinline__ uint32_t swaddr(uint32_t base, int r, int kb) {
    return base + (uint32_t)(r * 128) + (uint32_t)(((kb ^ (r & 7)) << 4));
}

// ---------------- K_prep: reset + weight conv + X hi/lo split (fused) -----
#define CXN (N_NODES * (HID / 4))
__global__ __launch_bounds__(256) void k_prep(
    const float* __restrict__ ue, const float* __restrict__ ie,
    const float* __restrict__ W,  const float* __restrict__ W1) {
    const int i = blockIdx.x * blockDim.x + threadIdx.x;
    if (i < CXN) {                              // X fp32 -> bf16 hi/lo, one float4
        int row = i >> 6, q = i & 63;
        const float* src = (row < N_USERS) ? (ue + (size_t)row * HID)
                                           : (ie + (size_t)(row - N_USERS) * HID);
        float4 v = ((const float4*)src)[q];
        __nv_bfloat162 h0 = __float22bfloat162_rn(make_float2(v.x, v.y));
        __nv_bfloat162 h1 = __float22bfloat162_rn(make_float2(v.z, v.w));
        float2 f0 = __bfloat1622float2(h0), f1 = __bfloat1622float2(h1);
        __nv_bfloat162 l0 = __float22bfloat162_rn(make_float2(v.x - f0.x, v.y - f0.y));
        __nv_bfloat162 l1 = __float22bfloat162_rn(make_float2(v.z - f1.x, v.w - f1.y));
        ((__nv_bfloat162*)g_Xhi)[i * 2]     = h0;
        ((__nv_bfloat162*)g_Xhi)[i * 2 + 1] = h1;
        ((__nv_bfloat162*)g_Xlo)[i * 2]     = l0;
        ((__nv_bfloat162*)g_Xlo)[i * 2 + 1] = l1;
    }
    if (i < HID * HID) {                        // gcn W^T split
        int n = i >> 8, k = i & 255;
        float v = W[k * HID + n];
        __nv_bfloat16 h = __float2bfloat16(v);
        g_Whi[i] = h;
        g_Wlo[i] = __float2bfloat16(v - __bfloat162float(h));
    }
    if (i < 2 * AH * HID) {                     // attn W1^T split: [half][n][k]
        int half = i >> 13, rem = i & 8191;
        int n = rem >> 8, k = rem & 255;
        float v = W1[(half * HID + k) * AH + n];
        __nv_bfloat16 h = __float2bfloat16(v);
        g_A1hi[i] = h;
        g_A1lo[i] = __float2bfloat16(v - __bfloat162float(h));
    }
    if (i < N_USERS) g_deg[i] = 1.0f;
    if (i == 0) { g_cnt[0] = 0; g_done = 0; g_maxpack = 0ull; }
}

// ---------------- K1: attention layer-1, 256-row CTAs ---------------------
#define AT_BSZ   16384
#define AT_AT    32768
#define AT_ASTG  (2 * AT_AT)
#define AT_SMEM  (2 * AT_BSZ + 2 * AT_ASTG)     // 160KB
#define N_UBLK   ((N_USERS + 255) / 256)        // 40
#define N_IBLK   ((N_ITEMS + 255) / 256)        // 118

__device__ __forceinline__ void at_stage_a(uint32_t sA, int row0, int ko, int rmax, int t) {
    #pragma unroll
    for (int i = t; i < 2048; i += 256) {
        int r = i >> 3, j = i & 7;
        int gr = row0 + r; if (gr > rmax) gr = rmax;
        size_t go = (size_t)gr * HID + ko + j * 8;
        uint32_t so = swaddr(sA, r, j);
        CP_ASYNC16(so,         g_Xhi + go);
        CP_ASYNC16(so + AT_AT, g_Xlo + go);
    }
}

__global__ __launch_bounds__(256, 1) void k_attn_mma(const float* __restrict__ b1) {
    extern __shared__ char smem[];
    const int t = threadIdx.x, l = t & 31, wrp = t >> 5;
    const int b = blockIdx.x;
    const int half = (b < N_UBLK) ? 0 : 1;
    const int row0 = half ? (N_USERS + (b - N_UBLK) * 256) : b * 256;
    const int rmax = half ? (N_NODES - 1) : (N_USERS - 1);

    const uint32_t sb  = smem_u32(smem);
    const uint32_t sBh = sb, sBl = sb + AT_BSZ, sA = sb + 2 * AT_BSZ;

    {   // B: 32 n-rows x 256 k, chunk-major (chunk c -> 32 rows x 128B)
        const __nv_bfloat16* srcH = g_A1hi + half * (AH * HID);
        const __nv_bfloat16* srcL = g_A1lo + half * (AH * HID);
        #pragma unroll
        for (int i = t; i < 1024; i += 256) {
            int c = i >> 8, n = (i >> 3) & 31, j = i & 7;
            size_t go = (size_t)n * HID + c * 64 + j * 8;
            uint32_t so = swaddr(c * 4096, n, j);
            CP_ASYNC16(sBh + so, srcH + go);
            CP_ASYNC16(sBl + so, srcL + go);
        }
    }
    at_stage_a(sA, row0, 0, rmax, t);
    CP_COMMIT();

    float acc[2][4][4] = {};
    const int rA = wrp * 32 + (l & 15);         // warp tile: 32 rows x 32 cols
    const int khalf = l >> 4;

    for (int c = 0; c < 4; c++) {
        if (c < 3) {
            at_stage_a(sA + ((c + 1) & 1) * AT_ASTG, row0, (c + 1) * 64, rmax, t);
            CP_COMMIT();
            CP_WAIT(1);
        } else {
            CP_WAIT(0);
        }
        __syncthreads();
        const uint32_t sAc = sA + (c & 1) * AT_ASTG;
        #pragma unroll
        for (int ks = 0; ks < 4; ks++) {
            const int kb = ks * 2 + khalf;
            uint32_t Ah[2][4], Al[2][4], Bh[2][4], Bl[2][4];
            ldsm4(Ah[0], swaddr(sAc, rA,      kb));
            ldsm4(Ah[1], swaddr(sAc, rA + 16, kb));
            ldsm4(Al[0], swaddr(sAc + AT_AT, rA,      kb));
            ldsm4(Al[1], swaddr(sAc + AT_AT, rA + 16, kb));
            ldsm4(Bh[0], swaddr(sBh + c * 4096, (l & 15),      kb));
            ldsm4(Bh[1], swaddr(sBh + c * 4096, 16 + (l & 15), kb));
            ldsm4(Bl[0], swaddr(sBl + c * 4096, (l & 15),      kb));
            ldsm4(Bl[1], swaddr(sBl + c * 4096, 16 + (l & 15), kb));
            #pragma unroll
            for (int mi = 0; mi < 2; mi++)
                #pragma unroll
                for (int nj = 0; nj < 4; nj++) {
                    const int nb = nj >> 1, p = nj & 1;
                    mma16816(acc[mi][nj], Ah[mi], Bh[nb][p], Bh[nb][p + 2]);
                    mma16816(acc[mi][nj], Ah[mi], Bl[nb][p], Bl[nb][p + 2]);
                    mma16816(acc[mi][nj], Al[mi], Bh[nb][p], Bh[nb][p + 2]);
                }
        }
        __syncthreads();
    }

    #pragma unroll
    for (int mi = 0; mi < 2; mi++) {
        #pragma unroll
        for (int h = 0; h < 2; h++) {
            const int r = row0 + wrp * 32 + mi * 16 + (l >> 2) + h * 8;
            if (r > rmax) continue;
            #pragma unroll
            for (int nj = 0; nj < 4; nj++) {
                const int col = nj * 8 + 2 * (l & 3);
                float x = acc[mi][nj][h * 2 + 0];
                float y = acc[mi][nj][h * 2 + 1];
                if (half) {
                    x += b1[col]; y += b1[col + 1];
                    *(float2*)(g_I1 + (size_t)(r - N_USERS) * AH + col) = make_float2(x, y);
                } else {
                    *(float2*)(g_U1 + (size_t)r * AH + col) = make_float2(x, y);
                }
            }
        }
    }
}

// ---------------- K2: edge MLP + denoise + compact + fallback + dinv ------
__global__ __launch_bounds__(256) void k_edge(
    const int* __restrict__ ei, const float* __restrict__ W2,
    const float* __restrict__ b2, float* __restrict__ out_w) {
    __shared__ float w2s[32];
    __shared__ float b2s;
    __shared__ int s_last;
    if (threadIdx.x < 32) w2s[threadIdx.x] = W2[threadIdx.x];
    if (threadIdx.x == 0) b2s = b2[0];
    __syncthreads();

    const int e = blockIdx.x * blockDim.x + threadIdx.x;
    bool pass = false;
    int s = 0, d = 0;
    unsigned long long pack = 0ull;
    if (e < N_EDGES) {
        s = ei[e];
        d = ei[N_EDGES + e];
        const float4* up = (const float4*)(g_U1 + (size_t)s * AH);
        const float4* ip = (const float4*)(g_I1 + (size_t)d * AH);
        float logit = b2s;
        #pragma unroll
        for (int q = 0; q < 8; q++) {
            float4 u = up[q], v = ip[q];
            float h;
            h = u.x + v.x; h = h > 0.0f ? h : 0.2f * h; logit = fmaf(h, w2s[q * 4 + 0], logit);
            h = u.y + v.y; h = h > 0.0f ? h : 0.2f * h; logit = fmaf(h, w2s[q * 4 + 1], logit);
            h = u.z + v.z; h = h > 0.0f ? h : 0.2f * h; logit = fmaf(h, w2s[q * 4 + 2], logit);
            h = u.w + v.w; h = h > 0.0f ? h : 0.2f * h; logit = fmaf(h, w2s[q * 4 + 3], logit);
        }
        float w = 1.0f / (1.0f + expf(-logit));
        pass = (w > 0.8f);
        out_w[e] = pass ? w : 0.0f;
        pack = ((unsigned long long)__float_as_uint(w) << 32)
             | (unsigned long long)(~(unsigned)e);
    }
    // argmax reduce (for fallback)
    unsigned long long pk = pack;
    #pragma unroll
    for (int off = 16; off; off >>= 1) {
        unsigned long long o = __shfl_down_sync(0xffffffffu, pk, off);
        if (o > pk) pk = o;
    }
    const int lane = threadIdx.x & 31;
    if (lane == 0) atomicMax(&g_maxpack, pk);
    // warp-aggregated compaction (no early return: all threads reach barriers)
    unsigned m = __ballot_sync(0xffffffffu, pass);
    if (m) {
        const int leader = __ffs(m) - 1;
        int base = 0;
        if (lane == leader) base = atomicAdd(&g_cnt[0], __popc(m));
        base = __shfl_sync(0xffffffffu, base, leader);
        if (pass) {
            const int rank = __popc(m & ((1u << lane) - 1));
            g_ksrc[base + rank] = s;
            g_kdst[base + rank] = d;
            atomicAdd(&g_deg[d], 1.0f);
        }
    }
    // last-block: fallback + dinv (threadfence + done-counter protocol)
    __threadfence();
    __syncthreads();
    if (threadIdx.x == 0)
        s_last = (atomicAdd(&g_done, 1) == (int)gridDim.x - 1) ? 1 : 0;
    __syncthreads();
    if (s_last) {
        if (threadIdx.x == 0 && g_cnt[0] == 0) {
            const unsigned long long p = g_maxpack;
            const int fe = (int)(~(unsigned)(p & 0xffffffffull));
            out_w[fe] = __uint_as_float((unsigned)(p >> 32));
            const int fs = ei[fe];
            const int fd = ei[N_EDGES + fe];
            g_ksrc[0] = fs;
            g_kdst[0] = fd;
            g_cnt[0] = 1;
            g_deg[fd] += 1.0f;
        }
        __syncthreads();
        #pragma unroll 4
        for (int i = threadIdx.x; i < N_USERS; i += 256)
            g_dinv[i] = rsqrtf(g_deg[i]);
    }
}

// ---------------- K5: HMMA bf16x3 GEMM, 512 threads / 16 warps ------------
// CTA: D[128x128] over K=256 in 4 chunks of 64; warp tile 32x32.
#define GT      16384
#define GSTAGE  (4 * GT)
#define GSMEM   (2 * GSTAGE)

__device__ __forceinline__ void stage_all(char* dst, int m0, int n0, int ko, int t) {
    uint32_t sb = smem_u32(dst);
    #pragma unroll
    for (int i = t; i < 1024; i += 512) {
        int r = i >> 3, kb = i & 7;
        int gr = m0 + r; if (gr > N_NODES - 1) gr = N_NODES - 1;
        size_t go = (size_t)gr * HID + ko + kb * 8;
        uint32_t so = sb + (uint32_t)(r * 128) + (uint32_t)(((kb ^ (r & 7)) << 4));
        CP_ASYNC16(so,          g_Xhi + go);
        CP_ASYNC16(so + GT,     g_Xlo + go);
        int br = n0 + r;
        size_t bo = (size_t)br * HID + ko + kb * 8;
        CP_ASYNC16(so + 2 * GT, g_Whi + bo);
        CP_ASYNC16(so + 3 * GT, g_Wlo + bo);
    }
}

__global__ __launch_bounds__(512, 1) void k_gemm(const float* __restrict__ gb,
                                                 float* __restrict__ out) {
    extern __shared__ char smem[];
    const int t = threadIdx.x;
    const int l = t & 31, wrp = t >> 5;         // 16 warps
    const int wm = wrp & 3, wn = wrp >> 2;      // 4x4 warp grid, tile 32x32
    const int m0 = blockIdx.x * 128, n0 = blockIdx.y * 128;
    const uint32_t sbase = smem_u32(smem);

    stage_all(smem, m0, n0, 0, t);
    CP_COMMIT();

    float acc[2][4][4] = {};
    const int rA = wm * 32 + (l & 15);
    const int rB = wn * 32 + (l & 15);
    const int khalf = l >> 4;

    for (int c = 0; c < 4; c++) {
        if (c < 3) {
            stage_all(smem + ((c + 1) & 1) * GSTAGE, m0, n0, (c + 1) * 64, t);
            CP_COMMIT();
            CP_WAIT(1);
        } else {
            CP_WAIT(0);
        }
        __syncthreads();
        const uint32_t sb  = sbase + (c & 1) * GSTAGE;
        const uint32_t sAh = sb, sAl = sb + GT, sBh = sb + 2 * GT, sBl = sb + 3 * GT;
        #pragma unroll
        for (int ks = 0; ks < 4; ks++) {
            const int kb = ks * 2 + khalf;
            uint32_t Ah[2][4], Al[2][4], Bh[2][4], Bl[2][4];
            ldsm4(Ah[0], swaddr(sAh, rA,      kb));
            ldsm4(Ah[1], swaddr(sAh, rA + 16, kb));
            ldsm4(Al[0], swaddr(sAl, rA,      kb));
            ldsm4(Al[1], swaddr(sAl, rA + 16, kb));
            ldsm4(Bh[0], swaddr(sBh, rB,      kb));
            ldsm4(Bh[1], swaddr(sBh, rB + 16, kb));
            ldsm4(Bl[0], swaddr(sBl, rB,      kb));
            ldsm4(Bl[1], swaddr(sBl, rB + 16, kb));
            #pragma unroll
            for (int mi = 0; mi < 2; mi++)
                #pragma unroll
                for (int nj = 0; nj < 4; nj++) {
                    const int nb = nj >> 1, p = nj & 1;
                    mma16816(acc[mi][nj], Ah[mi], Bh[nb][p], Bh[nb][p + 2]);
                    mma16816(acc[mi][nj], Ah[mi], Bl[nb][p], Bl[nb][p + 2]);
                    mma16816(acc[mi][nj], Al[mi], Bh[nb][p], Bh[nb][p + 2]);
                }
        }
        __syncthreads();
    }

    // epilogue: fused self-loop scaling + bias
    #pragma unroll
    for (int mi = 0; mi < 2; mi++) {
        #pragma unroll
        for (int h = 0; h < 2; h++) {
            const int row = m0 + wm * 32 + mi * 16 + (l >> 2) + h * 8;
            if (row >= N_NODES) continue;
            const bool isU = (row < N_USERS);
            const float dv  = isU ? g_dinv[row] : 1.0f;
            const float dsq = dv * dv;
            #pragma unroll
            for (int nj = 0; nj < 4; nj++) {
                const int col = n0 + wn * 32 + nj * 8 + 2 * (l & 3);
                const float x = acc[mi][nj][h * 2 + 0];
                const float y = acc[mi][nj][h * 2 + 1];
                const size_t off = (size_t)row * HID + col;
                if (isU) *(float2*)(g_xw + off) = make_float2(x, y);   // scatter reads users only
                const float2 bb = *(const float2*)(gb + col);
                *(float2*)(out + off) = make_float2(fmaf(x, dsq, bb.x), fmaf(y, dsq, bb.y));
            }
        }
    }
}

// ---------------- K6: scatter messages (vectorized L2 reductions) ---------
__global__ __launch_bounds__(256) void k_scatter(float* __restrict__ out) {
    const int kept = g_cnt[0];
    const long long total = (long long)kept * (HID / 4);
    const long long stride = (long long)gridDim.x * blockDim.x;
    for (long long idx = (long long)blockIdx.x * blockDim.x + threadIdx.x;
         idx < total; idx += stride) {
        const int i = (int)(idx >> 6);
        const int q = (int)(idx & 63);
        const int s = g_ksrc[i];
        const int d = g_kdst[i];
        const float coef = g_dinv[s] * g_dinv[d];
        float4 v = *(const float4*)(g_xw + (size_t)s * HID + q * 4);
        float* p = out + (size_t)d * HID + q * 4;
        asm volatile("red.global.add.v4.f32 [%0], {%1,%2,%3,%4};"
                     :: "l"(p), "f"(v.x * coef), "f"(v.y * coef),
                        "f"(v.z * coef), "f"(v.w * coef)
                     : "memory");
    }
}

// ---------------- host launch ---------------------------------------------
extern "C" void kernel_launch(void* const* d_in, const int* in_sizes, int n_in,
                              void* d_out, int out_size) {
    const float* ue = (const float*)d_in[0];
    const float* ie = (const float*)d_in[1];
    const int*   ei = (const int*)  d_in[2];
    const float* W1 = (const float*)d_in[3];
    const float* b1 = (const float*)d_in[4];
    const float* W2 = (const float*)d_in[5];
    const float* b2 = (const float*)d_in[6];
    const float* gW = (const float*)d_in[7];
    const float* gb = (const float*)d_in[8];
    float* out   = (float*)d_out;
    float* out_w = out + (size_t)N_NODES * HID;

    cudaFuncSetAttribute(k_gemm,     cudaFuncAttributeMaxDynamicSharedMemorySize, GSMEM);
    cudaFuncSetAttribute(k_attn_mma, cudaFuncAttributeMaxDynamicSharedMemorySize, AT_SMEM);

    k_prep<<<(CXN + 255) / 256, 256>>>(ue, ie, gW, W1);
    k_attn_mma<<<N_UBLK + N_IBLK, 256, AT_SMEM>>>(b1);
    k_edge<<<(N_EDGES + 255) / 256, 256>>>(ei, W2, b2, out_w);
    dim3 gg((N_NODES + 127) / 128, 2);
    k_gemm<<<gg, 512, GSMEM>>>(gb, out);
    k_scatter<<<1024, 256>>>(out);
}

// round 16
// speedup vs baseline: 1.1818x; 1.1655x over previous
#include <cuda_runtime.h>
#include <cuda_bf16.h>
#include <math.h>
#include <stdint.h>

#define N_USERS 10000
#define N_ITEMS 30000
#define N_NODES 40000
#define HID     256
#define N_EDGES 500000
#define AH      32

// ---------------- scratch (static device allocations only) ----------------
__device__ float g_U1[N_USERS * AH];
__device__ float g_I1[N_ITEMS * AH];
__device__ int   g_ksrc[N_EDGES];
__device__ int   g_kdst[N_EDGES];
__device__ float g_deg[N_USERS];
__device__ float g_dinv[N_USERS];
__device__ float g_xw[(size_t)N_USERS * HID];        // only user rows needed by scatter
__device__ int   g_cnt[1];                           // kept-edge count
__device__ unsigned long long g_maxpack;             // (w_bits<<32) | ~e
// bf16-split operands (K-major)
__device__ __align__(16) __nv_bfloat16 g_Xhi[(size_t)N_NODES * HID];
__device__ __align__(16) __nv_bfloat16 g_Xlo[(size_t)N_NODES * HID];
__device__ __align__(16) __nv_bfloat16 g_Whi[HID * HID];       // gcn W^T: [n][k]
__device__ __align__(16) __nv_bfloat16 g_Wlo[HID * HID];
__device__ __align__(16) __nv_bfloat16 g_A1hi[2 * AH * HID];   // attn W1^T: [half][n][k]
__device__ __align__(16) __nv_bfloat16 g_A1lo[2 * AH * HID];

// ---------------- helpers ---------------------------------------------------
__device__ __forceinline__ uint32_t smem_u32(const void* p) {
    uint32_t a;
    asm("{ .reg .u64 t; cvta.to.shared.u64 t, %1; cvt.u32.u64 %0, t; }" : "=r"(a) : "l"(p));
    return a;
}
__device__ __forceinline__ void ldsm4(uint32_t* f, uint32_t addr) {
    asm volatile("ldmatrix.sync.aligned.m8n8.x4.shared.b16 {%0,%1,%2,%3}, [%4];"
        : "=r"(f[0]), "=r"(f[1]), "=r"(f[2]), "=r"(f[3]) : "r"(addr));
}
__device__ __forceinline__ void mma16816(float* d, const uint32_t* a, uint32_t b0, uint32_t b1) {
    asm volatile("mma.sync.aligned.m16n8k16.row.col.f32.bf16.bf16.f32 "
        "{%0,%1,%2,%3}, {%4,%5,%6,%7}, {%8,%9}, {%0,%1,%2,%3};"
        : "+f"(d[0]), "+f"(d[1]), "+f"(d[2]), "+f"(d[3])
        : "r"(a[0]), "r"(a[1]), "r"(a[2]), "r"(a[3]), "r"(b0), "r"(b1));
}
#define CP_ASYNC16(s, g) asm volatile("cp.async.cg.shared.global [%0], [%1], 16;" :: "r"(s), "l"(g))
#define CP_COMMIT()      asm volatile("cp.async.commit_group;" ::: "memory")
#define CP_WAIT(n)       asm volatile("cp.async.wait_group %0;" :: "n"(n) : "memory")

__device__ __forceinline__ uint32_t swaddr(uint32_t base, int r, int kb) {
    return base + (uint32_t)(r * 128) + (uint32_t)(((kb ^ (r & 7)) << 4));
}

// ---------------- K_prep: reset + weight conv + X hi/lo split (fused) -----
#define CXN (N_NODES * (HID / 4))
__global__ __launch_bounds__(256) void k_prep(
    const float* __restrict__ ue, const float* __restrict__ ie,
    const float* __restrict__ W,  const float* __restrict__ W1) {
    const int i = blockIdx.x * blockDim.x + threadIdx.x;
    if (i < CXN) {                              // X fp32 -> bf16 hi/lo, one float4
        int row = i >> 6, q = i & 63;
        const float* src = (row < N_USERS) ? (ue + (size_t)row * HID)
                                           : (ie + (size_t)(row - N_USERS) * HID);
        float4 v = ((const float4*)src)[q];
        __nv_bfloat162 h0 = __float22bfloat162_rn(make_float2(v.x, v.y));
        __nv_bfloat162 h1 = __float22bfloat162_rn(make_float2(v.z, v.w));
        float2 f0 = __bfloat1622float2(h0), f1 = __bfloat1622float2(h1);
        __nv_bfloat162 l0 = __float22bfloat162_rn(make_float2(v.x - f0.x, v.y - f0.y));
        __nv_bfloat162 l1 = __float22bfloat162_rn(make_float2(v.z - f1.x, v.w - f1.y));
        ((__nv_bfloat162*)g_Xhi)[i * 2]     = h0;
        ((__nv_bfloat162*)g_Xhi)[i * 2 + 1] = h1;
        ((__nv_bfloat162*)g_Xlo)[i * 2]     = l0;
        ((__nv_bfloat162*)g_Xlo)[i * 2 + 1] = l1;
    }
    if (i < HID * HID) {                        // gcn W^T split
        int n = i >> 8, k = i & 255;
        float v = W[k * HID + n];
        __nv_bfloat16 h = __float2bfloat16(v);
        g_Whi[i] = h;
        g_Wlo[i] = __float2bfloat16(v - __bfloat162float(h));
    }
    if (i < 2 * AH * HID) {                     // attn W1^T split: [half][n][k]
        int half = i >> 13, rem = i & 8191;
        int n = rem >> 8, k = rem & 255;
        float v = W1[(half * HID + k) * AH + n];
        __nv_bfloat16 h = __float2bfloat16(v);
        g_A1hi[i] = h;
        g_A1lo[i] = __float2bfloat16(v - __bfloat162float(h));
    }
    if (i < N_USERS) g_deg[i] = 1.0f;
    if (i == 0) { g_cnt[0] = 0; g_maxpack = 0ull; }
}

// ---------------- K1: attention layer-1, 256-row CTAs ---------------------
#define AT_BSZ   16384
#define AT_AT    32768
#define AT_ASTG  (2 * AT_AT)
#define AT_SMEM  (2 * AT_BSZ + 2 * AT_ASTG)     // 160KB
#define N_UBLK   ((N_USERS + 255) / 256)        // 40
#define N_IBLK   ((N_ITEMS + 255) / 256)        // 118

__device__ __forceinline__ void at_stage_a(uint32_t sA, int row0, int ko, int rmax, int t) {
    #pragma unroll
    for (int i = t; i < 2048; i += 256) {
        int r = i >> 3, j = i & 7;
        int gr = row0 + r; if (gr > rmax) gr = rmax;
        size_t go = (size_t)gr * HID + ko + j * 8;
        uint32_t so = swaddr(sA, r, j);
        CP_ASYNC16(so,         g_Xhi + go);
        CP_ASYNC16(so + AT_AT, g_Xlo + go);
    }
}

__global__ __launch_bounds__(256, 1) void k_attn_mma(const float* __restrict__ b1) {
    extern __shared__ char smem[];
    const int t = threadIdx.x, l = t & 31, wrp = t >> 5;
    const int b = blockIdx.x;
    const int half = (b < N_UBLK) ? 0 : 1;
    const int row0 = half ? (N_USERS + (b - N_UBLK) * 256) : b * 256;
    const int rmax = half ? (N_NODES - 1) : (N_USERS - 1);

    const uint32_t sb  = smem_u32(smem);
    const uint32_t sBh = sb, sBl = sb + AT_BSZ, sA = sb + 2 * AT_BSZ;

    {   // B: 32 n-rows x 256 k, chunk-major (chunk c -> 32 rows x 128B)
        const __nv_bfloat16* srcH = g_A1hi + half * (AH * HID);
        const __nv_bfloat16* srcL = g_A1lo + half * (AH * HID);
        #pragma unroll
        for (int i = t; i < 1024; i += 256) {
            int c = i >> 8, n = (i >> 3) & 31, j = i & 7;
            size_t go = (size_t)n * HID + c * 64 + j * 8;
            uint32_t so = swaddr(c * 4096, n, j);
            CP_ASYNC16(sBh + so, srcH + go);
            CP_ASYNC16(sBl + so, srcL + go);
        }
    }
    at_stage_a(sA, row0, 0, rmax, t);
    CP_COMMIT();

    float acc[2][4][4] = {};
    const int rA = wrp * 32 + (l & 15);         // warp tile: 32 rows x 32 cols
    const int khalf = l >> 4;

    for (int c = 0; c < 4; c++) {
        if (c < 3) {
            at_stage_a(sA + ((c + 1) & 1) * AT_ASTG, row0, (c + 1) * 64, rmax, t);
            CP_COMMIT();
            CP_WAIT(1);
        } else {
            CP_WAIT(0);
        }
        __syncthreads();
        const uint32_t sAc = sA + (c & 1) * AT_ASTG;
        #pragma unroll
        for (int ks = 0; ks < 4; ks++) {
            const int kb = ks * 2 + khalf;
            uint32_t Ah[2][4], Al[2][4], Bh[2][4], Bl[2][4];
            ldsm4(Ah[0], swaddr(sAc, rA,      kb));
            ldsm4(Ah[1], swaddr(sAc, rA + 16, kb));
            ldsm4(Al[0], swaddr(sAc + AT_AT, rA,      kb));
            ldsm4(Al[1], swaddr(sAc + AT_AT, rA + 16, kb));
            ldsm4(Bh[0], swaddr(sBh + c * 4096, (l & 15),      kb));
            ldsm4(Bh[1], swaddr(sBh + c * 4096, 16 + (l & 15), kb));
            ldsm4(Bl[0], swaddr(sBl + c * 4096, (l & 15),      kb));
            ldsm4(Bl[1], swaddr(sBl + c * 4096, 16 + (l & 15), kb));
            #pragma unroll
            for (int mi = 0; mi < 2; mi++)
                #pragma unroll
                for (int nj = 0; nj < 4; nj++) {
                    const int nb = nj >> 1, p = nj & 1;
                    mma16816(acc[mi][nj], Ah[mi], Bh[nb][p], Bh[nb][p + 2]);
                    mma16816(acc[mi][nj], Ah[mi], Bl[nb][p], Bl[nb][p + 2]);
                    mma16816(acc[mi][nj], Al[mi], Bh[nb][p], Bh[nb][p + 2]);
                }
        }
        __syncthreads();
    }

    #pragma unroll
    for (int mi = 0; mi < 2; mi++) {
        #pragma unroll
        for (int h = 0; h < 2; h++) {
            const int r = row0 + wrp * 32 + mi * 16 + (l >> 2) + h * 8;
            if (r > rmax) continue;
            #pragma unroll
            for (int nj = 0; nj < 4; nj++) {
                const int col = nj * 8 + 2 * (l & 3);
                float x = acc[mi][nj][h * 2 + 0];
                float y = acc[mi][nj][h * 2 + 1];
                if (half) {
                    x += b1[col]; y += b1[col + 1];
                    *(float2*)(g_I1 + (size_t)(r - N_USERS) * AH + col) = make_float2(x, y);
                } else {
                    *(float2*)(g_U1 + (size_t)r * AH + col) = make_float2(x, y);
                }
            }
        }
    }
}

// ---------------- K2: edge MLP + sigmoid + compact (fence-free) -----------
__global__ __launch_bounds__(256) void k_edge(
    const int* __restrict__ ei, const float* __restrict__ W2,
    const float* __restrict__ b2, float* __restrict__ out_w) {
    __shared__ float w2s[32];
    __shared__ float b2s;
    if (threadIdx.x < 32) w2s[threadIdx.x] = W2[threadIdx.x];
    if (threadIdx.x == 0) b2s = b2[0];
    __syncthreads();

    const int e = blockIdx.x * blockDim.x + threadIdx.x;
    bool pass = false;
    int s = 0, d = 0;
    unsigned long long pack = 0ull;
    if (e < N_EDGES) {
        s = ei[e];
        d = ei[N_EDGES + e];
        const float4* up = (const float4*)(g_U1 + (size_t)s * AH);
        const float4* ip = (const float4*)(g_I1 + (size_t)d * AH);
        float logit = b2s;
        #pragma unroll
        for (int q = 0; q < 8; q++) {
            float4 u = up[q], v = ip[q];
            float h;
            h = u.x + v.x; h = h > 0.0f ? h : 0.2f * h; logit = fmaf(h, w2s[q * 4 + 0], logit);
            h = u.y + v.y; h = h > 0.0f ? h : 0.2f * h; logit = fmaf(h, w2s[q * 4 + 1], logit);
            h = u.z + v.z; h = h > 0.0f ? h : 0.2f * h; logit = fmaf(h, w2s[q * 4 + 2], logit);
            h = u.w + v.w; h = h > 0.0f ? h : 0.2f * h; logit = fmaf(h, w2s[q * 4 + 3], logit);
        }
        float w = 1.0f / (1.0f + expf(-logit));
        pass = (w > 0.8f);
        out_w[e] = pass ? w : 0.0f;
        pack = ((unsigned long long)__float_as_uint(w) << 32)
             | (unsigned long long)(~(unsigned)e);
    }
    // argmax reduce (for fallback)
    unsigned long long pk = pack;
    #pragma unroll
    for (int off = 16; off; off >>= 1) {
        unsigned long long o = __shfl_down_sync(0xffffffffu, pk, off);
        if (o > pk) pk = o;
    }
    const int lane = threadIdx.x & 31;
    if (lane == 0) atomicMax(&g_maxpack, pk);
    // warp-aggregated compaction
    unsigned m = __ballot_sync(0xffffffffu, pass);
    if (!m) return;
    const int leader = __ffs(m) - 1;
    int base = 0;
    if (lane == leader) base = atomicAdd(&g_cnt[0], __popc(m));
    base = __shfl_sync(0xffffffffu, base, leader);
    if (pass) {
        const int rank = __popc(m & ((1u << lane) - 1));
        g_ksrc[base + rank] = s;
        g_kdst[base + rank] = d;
        atomicAdd(&g_deg[d], 1.0f);
    }
}

// ---------------- K3: post (fallback + dinv, single block) ----------------
__global__ __launch_bounds__(1024) void k_post(const int* __restrict__ ei,
                                               float* __restrict__ out_w) {
    if (threadIdx.x == 0 && g_cnt[0] == 0) {
        const unsigned long long p = g_maxpack;
        const int fe = (int)(~(unsigned)(p & 0xffffffffull));
        out_w[fe] = __uint_as_float((unsigned)(p >> 32));
        const int fs = ei[fe];
        const int fd = ei[N_EDGES + fe];
        g_ksrc[0] = fs;
        g_kdst[0] = fd;
        g_cnt[0] = 1;
        g_deg[fd] += 1.0f;
    }
    __syncthreads();
    #pragma unroll 2
    for (int i = threadIdx.x; i < N_USERS; i += 1024)
        g_dinv[i] = rsqrtf(g_deg[i]);
}

// ---------------- K5: HMMA bf16x3 GEMM, 128x64 tiles, 2 CTAs/SM -----------
// CTA: D[128x64] over K=256 in 4 chunks of 64; 8 warps, warp tile 32x32.
// smem/stage: A hi/lo (2x16KB) + B hi/lo (2x8KB) = 48KB; double buffer = 96KB total.
#define GT      16384
#define BT      8192
#define GSTAGE  (2 * GT + 2 * BT)
#define GSMEM   (2 * GSTAGE)                    // 98304 bytes per CTA

__device__ __forceinline__ void stage_all(char* dst, int m0, int n0, int ko, int t) {
    uint32_t sb = smem_u32(dst);
    #pragma unroll
    for (int i = t; i < 1536; i += 256) {
        if (i < 1024) {                         // A: 128 rows x 8 chunks
            int r = i >> 3, kb = i & 7;
            int gr = m0 + r; if (gr > N_NODES - 1) gr = N_NODES - 1;
            size_t go = (size_t)gr * HID + ko + kb * 8;
            uint32_t so = swaddr(sb, r, kb);
            CP_ASYNC16(so,      g_Xhi + go);
            CP_ASYNC16(so + GT, g_Xlo + go);
        } else {                                // B: 64 rows x 8 chunks
            int j = i - 1024;
            int r = j >> 3, kb = j & 7;
            size_t bo = (size_t)(n0 + r) * HID + ko + kb * 8;
            uint32_t so = swaddr(sb + 2 * GT, r, kb);
            CP_ASYNC16(so,      g_Whi + bo);
            CP_ASYNC16(so + BT, g_Wlo + bo);
        }
    }
}

__global__ __launch_bounds__(256, 2) void k_gemm(const float* __restrict__ gb,
                                                 float* __restrict__ out) {
    extern __shared__ char smem[];
    const int t = threadIdx.x;
    const int l = t & 31, wrp = t >> 5;         // 8 warps
    const int wm = wrp & 3, wn = wrp >> 2;      // 4x2 warp grid, tile 32x32
    const int m0 = blockIdx.x * 128, n0 = blockIdx.y * 64;
    const uint32_t sbase = smem_u32(smem);

    stage_all(smem, m0, n0, 0, t);
    CP_COMMIT();

    float acc[2][4][4] = {};
    const int rA = wm * 32 + (l & 15);
    const int rB = wn * 32 + (l & 15);
    const int khalf = l >> 4;

    for (int c = 0; c < 4; c++) {
        if (c < 3) {
            stage_all(smem + ((c + 1) & 1) * GSTAGE, m0, n0, (c + 1) * 64, t);
            CP_COMMIT();
            CP_WAIT(1);
        } else {
            CP_WAIT(0);
        }
        __syncthreads();
        const uint32_t sb  = sbase + (c & 1) * GSTAGE;
        const uint32_t sAh = sb, sAl = sb + GT, sBh = sb + 2 * GT, sBl = sb + 2 * GT + BT;
        #pragma unroll
        for (int ks = 0; ks < 4; ks++) {
            const int kb = ks * 2 + khalf;
            uint32_t Ah[2][4], Al[2][4], Bh[2][4], Bl[2][4];
            ldsm4(Ah[0], swaddr(sAh, rA,      kb));
            ldsm4(Ah[1], swaddr(sAh, rA + 16, kb));
            ldsm4(Al[0], swaddr(sAl, rA,      kb));
            ldsm4(Al[1], swaddr(sAl, rA + 16, kb));
            ldsm4(Bh[0], swaddr(sBh, rB,      kb));
            ldsm4(Bh[1], swaddr(sBh, rB + 16, kb));
            ldsm4(Bl[0], swaddr(sBl, rB,      kb));
            ldsm4(Bl[1], swaddr(sBl, rB + 16, kb));
            #pragma unroll
            for (int mi = 0; mi < 2; mi++)
                #pragma unroll
                for (int nj = 0; nj < 4; nj++) {
                    const int nb = nj >> 1, p = nj & 1;
                    mma16816(acc[mi][nj], Ah[mi], Bh[nb][p], Bh[nb][p + 2]);
                    mma16816(acc[mi][nj], Ah[mi], Bl[nb][p], Bl[nb][p + 2]);
                    mma16816(acc[mi][nj], Al[mi], Bh[nb][p], Bh[nb][p + 2]);
                }
        }
        __syncthreads();
    }

    // epilogue: fused self-loop scaling + bias
    #pragma unroll
    for (int mi = 0; mi < 2; mi++) {
        #pragma unroll
        for (int h = 0; h < 2; h++) {
            const int row = m0 + wm * 32 + mi * 16 + (l >> 2) + h * 8;
            if (row >= N_NODES) continue;
            const bool isU = (row < N_USERS);
            const float dv  = isU ? g_dinv[row] : 1.0f;
            const float dsq = dv * dv;
            #pragma unroll
            for (int nj = 0; nj < 4; nj++) {
                const int col = n0 + wn * 32 + nj * 8 + 2 * (l & 3);
                const float x = acc[mi][nj][h * 2 + 0];
                const float y = acc[mi][nj][h * 2 + 1];
                const size_t off = (size_t)row * HID + col;
                if (isU) *(float2*)(g_xw + off) = make_float2(x, y);   // scatter reads users only
                const float2 bb = *(const float2*)(gb + col);
                *(float2*)(out + off) = make_float2(fmaf(x, dsq, bb.x), fmaf(y, dsq, bb.y));
            }
        }
    }
}

// ---------------- K6: scatter messages (vectorized L2 reductions) ---------
__global__ __launch_bounds__(256) void k_scatter(float* __restrict__ out) {
    const int kept = g_cnt[0];
    const long long total = (long long)kept * (HID / 4);
    const long long stride = (long long)gridDim.x * blockDim.x;
    for (long long idx = (long long)blockIdx.x * blockDim.x + threadIdx.x;
         idx < total; idx += stride) {
        const int i = (int)(idx >> 6);
        const int q = (int)(idx & 63);
        const int s = g_ksrc[i];
        const int d = g_kdst[i];
        const float coef = g_dinv[s] * g_dinv[d];
        float4 v = *(const float4*)(g_xw + (size_t)s * HID + q * 4);
        float* p = out + (size_t)d * HID + q * 4;
        asm volatile("red.global.add.v4.f32 [%0], {%1,%2,%3,%4};"
                     :: "l"(p), "f"(v.x * coef), "f"(v.y * coef),
                        "f"(v.z * coef), "f"(v.w * coef)
                     : "memory");
    }
}

// ---------------- host launch ---------------------------------------------
extern "C" void kernel_launch(void* const* d_in, const int* in_sizes, int n_in,
                              void* d_out, int out_size) {
    const float* ue = (const float*)d_in[0];
    const float* ie = (const float*)d_in[1];
    const int*   ei = (const int*)  d_in[2];
    const float* W1 = (const float*)d_in[3];
    const float* b1 = (const float*)d_in[4];
    const float* W2 = (const float*)d_in[5];
    const float* b2 = (const float*)d_in[6];
    const float* gW = (const float*)d_in[7];
    const float* gb = (const float*)d_in[8];
    float* out   = (float*)d_out;
    float* out_w = out + (size_t)N_NODES * HID;

    cudaFuncSetAttribute(k_gemm,     cudaFuncAttributeMaxDynamicSharedMemorySize, GSMEM);
    cudaFuncSetAttribute(k_attn_mma, cudaFuncAttributeMaxDynamicSharedMemorySize, AT_SMEM);

    k_prep<<<(CXN + 255) / 256, 256>>>(ue, ie, gW, W1);
    k_attn_mma<<<N_UBLK + N_IBLK, 256, AT_SMEM>>>(b1);
    k_edge<<<(N_EDGES + 255) / 256, 256>>>(ei, W2, b2, out_w);
    k_post<<<1, 1024>>>(ei, out_w);
    dim3 gg((N_NODES + 127) / 128, 4);
    k_gemm<<<gg, 256, GSMEM>>>(gb, out);        // 96KB per CTA -> 2 CTAs/SM
    k_scatter<<<1024, 256>>>(out);
}